// round 1
// baseline (speedup 1.0000x reference)
#include <cuda_runtime.h>
#include <math.h>

#define N_UNIQ 20000
#define D_IN   128
#define D_OUT  384
#define K_NB   32
#define B_OUT  40000

#define BM 128
#define BN 128
#define BK 16

// Scratch (static __device__ globals per harness rules)
__device__ __align__(128) float g_M[D_OUT * D_OUT];   // combined weight [384][384]
__device__ __align__(128) float g_c[D_OUT];           // combined bias
__device__ __align__(128) float g_X[N_UNIQ * D_OUT];  // [self | adj_mean | dis_mean]
__device__ __align__(128) float g_Z[N_UNIQ * D_OUT];  // leaky(X@M + c), unnormalized
__device__ __align__(128) float g_ss[N_UNIQ];         // per-row sum of squares

// ---------------------------------------------------------------------------
// Kernel 1: M = stack(W_self@WC[0:128,:], W_adj@WC[128:256,:], W_dis@WC[256:384,:])
//           c = bias @ WC + WC_b
// grid 385 blocks x 384 threads. Tiny (~19 MFLOP), L2-resident.
// ---------------------------------------------------------------------------
__global__ void combine_kernel(const float* __restrict__ Ws,
                               const float* __restrict__ Wa,
                               const float* __restrict__ Wd,
                               const float* __restrict__ WC,
                               const float* __restrict__ bias,
                               const float* __restrict__ WCb) {
    int j = threadIdx.x;      // 0..383 output column
    int r = blockIdx.x;       // 0..383 = row of M, 384 = c
    if (r < D_OUT) {
        int part = r >> 7;    // 0,1,2
        int i = r & 127;
        const float* W = (part == 0) ? Ws : ((part == 1) ? Wa : Wd);
        float acc = 0.f;
#pragma unroll 4
        for (int o = 0; o < 128; o++)
            acc += __ldg(&W[i * 128 + o]) * WC[(part * 128 + o) * D_OUT + j];
        g_M[r * D_OUT + j] = acc;
    } else {
        float acc = WCb[j];
        for (int i = 0; i < D_OUT; i++)
            acc += bias[i] * WC[i * D_OUT + j];
        g_c[j] = acc;
    }
}

// ---------------------------------------------------------------------------
// Kernel 2: aggregation. One block per unique node, 128 threads (one per dim).
// X[n] = [ feat[uniq[n]] | mean_k feat[adj[n,k]] | mean_k feat[dis[n,k]] ]
// Also zeroes g_ss[n]. Memory bound: ~655 MB of random 512B-row reads.
// ---------------------------------------------------------------------------
__global__ __launch_bounds__(128) void agg_kernel(const int* __restrict__ uniq,
                                                  const int* __restrict__ adj,
                                                  const int* __restrict__ dis,
                                                  const float* __restrict__ feat) {
    int n = blockIdx.x;
    int d = threadIdx.x;
    __shared__ int s_adj[K_NB];
    __shared__ int s_dis[K_NB];
    __shared__ int s_u;
    if (d < K_NB)            s_adj[d] = adj[n * K_NB + d];
    else if (d < 2 * K_NB)   s_dis[d - K_NB] = dis[n * K_NB + (d - K_NB)];
    else if (d == 64)        s_u = uniq[n];
    else if (d == 96)        g_ss[n] = 0.f;
    __syncthreads();

    float a = 0.f, b = 0.f;
#pragma unroll 8
    for (int k = 0; k < K_NB; k++)
        a += __ldg(&feat[(long)s_adj[k] * D_IN + d]);
#pragma unroll 8
    for (int k = 0; k < K_NB; k++)
        b += __ldg(&feat[(long)s_dis[k] * D_IN + d]);
    float sf = __ldg(&feat[(long)s_u * D_IN + d]);

    g_X[n * D_OUT + d]           = sf;
    g_X[n * D_OUT + 128 + d]     = a * (1.f / 32.f);
    g_X[n * D_OUT + 256 + d]     = b * (1.f / 32.f);
}

// ---------------------------------------------------------------------------
// Kernel 3: Z = leakyrelu(X @ M + c), g_ss[row] += sum_j Z[row,j]^2
// Classic 128x128 tile, BK=16, 256 threads, 8x8 per-thread, double buffered.
// grid (ceil(20000/128)=157, 3)
// ---------------------------------------------------------------------------
__global__ __launch_bounds__(256) void gemm_kernel(int Mrows) {
    __shared__ float sA[2][BK][BM + 4];  // transposed: sA[k][m]
    __shared__ float sB[2][BK][BN];      // sB[k][n]

    const int tid  = threadIdx.x;
    const int tx   = tid & 15;     // col group
    const int ty   = tid >> 4;     // row group
    const int row0 = blockIdx.x * BM;
    const int col0 = blockIdx.y * BN;

    float acc[8][8];
#pragma unroll
    for (int i = 0; i < 8; i++)
#pragma unroll
        for (int j = 0; j < 8; j++) acc[i][j] = 0.f;

    // ---- load helpers (2 float4 per thread per tile for each of A,B) ----
    float4 aR[2], bR[2];

    auto fetch = [&](int kb) {
#pragma unroll
        for (int it = 0; it < 2; it++) {
            int id = tid + 256 * it;
            int ar = id >> 2, kk = (id & 3) << 2;
            int grow = row0 + ar;
            if (grow < Mrows)
                aR[it] = *reinterpret_cast<const float4*>(&g_X[grow * D_OUT + kb + kk]);
            else
                aR[it] = make_float4(0.f, 0.f, 0.f, 0.f);
            int br = id >> 5, nn = (id & 31) << 2;
            bR[it] = *reinterpret_cast<const float4*>(&g_M[(kb + br) * D_OUT + col0 + nn]);
        }
    };
    auto stage = [&](int buf) {
#pragma unroll
        for (int it = 0; it < 2; it++) {
            int id = tid + 256 * it;
            int ar = id >> 2, kk = (id & 3) << 2;
            sA[buf][kk + 0][ar] = aR[it].x;
            sA[buf][kk + 1][ar] = aR[it].y;
            sA[buf][kk + 2][ar] = aR[it].z;
            sA[buf][kk + 3][ar] = aR[it].w;
            int br = id >> 5, nn = (id & 31) << 2;
            *reinterpret_cast<float4*>(&sB[buf][br][nn]) = bR[it];
        }
    };

    const int nK = D_OUT / BK;  // 24
    fetch(0);
    stage(0);
    __syncthreads();

    for (int t = 0; t < nK; t++) {
        int buf = t & 1;
        if (t + 1 < nK) fetch((t + 1) * BK);
#pragma unroll
        for (int k = 0; k < BK; k++) {
            float a[8], b[8];
            *reinterpret_cast<float4*>(&a[0]) = *reinterpret_cast<float4*>(&sA[buf][k][ty * 8]);
            *reinterpret_cast<float4*>(&a[4]) = *reinterpret_cast<float4*>(&sA[buf][k][ty * 8 + 4]);
            *reinterpret_cast<float4*>(&b[0]) = *reinterpret_cast<float4*>(&sB[buf][k][tx * 8]);
            *reinterpret_cast<float4*>(&b[4]) = *reinterpret_cast<float4*>(&sB[buf][k][tx * 8 + 4]);
#pragma unroll
            for (int i = 0; i < 8; i++)
#pragma unroll
                for (int j = 0; j < 8; j++)
                    acc[i][j] += a[i] * b[j];
        }
        if (t + 1 < nK) {
            stage(buf ^ 1);
            __syncthreads();
        }
    }

    // ---- epilogue: +c, leaky relu, store, per-row sum-of-squares ----
    float cv[8];
#pragma unroll
    for (int j = 0; j < 8; j++) cv[j] = g_c[col0 + tx * 8 + j];

#pragma unroll
    for (int i = 0; i < 8; i++) {
        int grow = row0 + ty * 8 + i;
        bool valid = (grow < Mrows);
        float zz[8];
        float ss = 0.f;
#pragma unroll
        for (int j = 0; j < 8; j++) {
            float z = acc[i][j] + cv[j];
            z = (z >= 0.f) ? z : 0.2f * z;
            zz[j] = z;
            ss += z * z;
        }
        if (valid) {
            *reinterpret_cast<float4*>(&g_Z[grow * D_OUT + col0 + tx * 8])     =
                make_float4(zz[0], zz[1], zz[2], zz[3]);
            *reinterpret_cast<float4*>(&g_Z[grow * D_OUT + col0 + tx * 8 + 4]) =
                make_float4(zz[4], zz[5], zz[6], zz[7]);
        }
        // reduce ss across the 16 lanes that share this row (tx = low 4 lane bits)
        ss += __shfl_xor_sync(0xffffffffu, ss, 1);
        ss += __shfl_xor_sync(0xffffffffu, ss, 2);
        ss += __shfl_xor_sync(0xffffffffu, ss, 4);
        ss += __shfl_xor_sync(0xffffffffu, ss, 8);
        if (tx == 0 && valid) atomicAdd(&g_ss[grow], ss);
    }
}

// ---------------------------------------------------------------------------
// Kernel 4: out[b] = Z[idx[b]] / max(||Z[idx[b]]||, 1e-12)
// One block per output row; float4 moves. Z is L2-resident (30 MB).
// ---------------------------------------------------------------------------
__global__ __launch_bounds__(128) void gather_kernel(const int* __restrict__ nidx,
                                                     float* __restrict__ out) {
    int b = blockIdx.x;
    int t = threadIdx.x;
    int idx = __ldg(&nidx[b]);
    float s = g_ss[idx];
    float norm = fmaxf(sqrtf(s), 1e-12f);
    float inv = 1.f / norm;
    if (t < 96) {  // 96 float4 = 384 floats
        const float4* zp = reinterpret_cast<const float4*>(&g_Z[(long)idx * D_OUT]);
        float4* op = reinterpret_cast<float4*>(&out[(long)b * D_OUT]);
        float4 v = zp[t];
        v.x *= inv; v.y *= inv; v.z *= inv; v.w *= inv;
        op[t] = v;
    }
}

// ---------------------------------------------------------------------------
extern "C" void kernel_launch(void* const* d_in, const int* in_sizes, int n_in,
                              void* d_out, int out_size) {
    const int*   uniq = (const int*)d_in[0];
    const int*   adj  = (const int*)d_in[1];
    const int*   dis  = (const int*)d_in[2];
    const int*   nidx = (const int*)d_in[3];
    const float* feat = (const float*)d_in[4];
    const float* Ws   = (const float*)d_in[5];
    const float* Wa   = (const float*)d_in[6];
    const float* Wd   = (const float*)d_in[7];
    const float* bias = (const float*)d_in[8];
    const float* WC   = (const float*)d_in[9];
    const float* WCb  = (const float*)d_in[10];
    float* out = (float*)d_out;

    combine_kernel<<<D_OUT + 1, D_OUT>>>(Ws, Wa, Wd, WC, bias, WCb);
    agg_kernel<<<N_UNIQ, 128>>>(uniq, adj, dis, feat);
    dim3 ggrid((N_UNIQ + BM - 1) / BM, D_OUT / BN);
    gemm_kernel<<<ggrid, 256>>>(N_UNIQ);
    gather_kernel<<<B_OUT, 128>>>(nidx, out);
}

// round 3
// speedup vs baseline: 1.4329x; 1.4329x over previous
#include <cuda_runtime.h>
#include <cuda_bf16.h>
#include <math.h>
#include <stdint.h>

#define N_UNIQ 20000
#define D_IN   128
#define D_OUT  384
#define K_NB   32
#define B_OUT  40000

#define KP        768          // split-K storage: [hi 384 | lo 384]
#define ROWS_PAD  20096        // 157 * 128
#define N_CTAS_M  157
#define NCHUNK    36           // 3 segments x 12 chunks of BK=32

// ---------------- scratch (__device__ globals; zero-init once) --------------
__device__ __align__(128) __nv_bfloat16 g_Xs[ROWS_PAD * KP];  // A, hi|lo
__device__ __align__(128) __nv_bfloat16 g_Bt[D_OUT * KP];     // B [n][k], hi|lo
__device__ __align__(128) float g_c[D_OUT];                   // fused bias
__device__ __align__(128) float g_Z[ROWS_PAD * D_OUT];        // unnormalized out
__device__ __align__(128) float g_ss[ROWS_PAD];               // per-row sum sq

// ---------------- helpers ----------------------------------------------------
__device__ __forceinline__ uint32_t smem_u32(const void* p) {
    uint32_t a;
    asm("{ .reg .u64 t; cvta.to.shared.u64 t, %1; cvt.u32.u64 %0, t; }" : "=r"(a) : "l"(p));
    return a;
}
#define LDMATRIX_X4(r0, r1, r2, r3, addr) \
    asm volatile("ldmatrix.sync.aligned.m8n8.x4.shared.b16 {%0,%1,%2,%3}, [%4];" \
                 : "=r"(r0), "=r"(r1), "=r"(r2), "=r"(r3) : "r"(addr))
#define MMA_16816(d, a, b0, b1) \
    asm volatile("mma.sync.aligned.m16n8k16.row.col.f32.bf16.bf16.f32 " \
                 "{%0,%1,%2,%3}, {%4,%5,%6,%7}, {%8,%9}, {%0,%1,%2,%3};" \
                 : "+f"((d)[0]), "+f"((d)[1]), "+f"((d)[2]), "+f"((d)[3]) \
                 : "r"((a)[0]), "r"((a)[1]), "r"((a)[2]), "r"((a)[3]), \
                   "r"(b0), "r"(b1))

// ---------------------------------------------------------------------------
// Kernel 1: fused weight (transposed [n][k], bf16 hi|lo split) + fused bias.
//   M[k][n] = sum_o W_part(k)[k%128][o] * WC[part*128+o][n];  c = bias@WC + WCb
// ---------------------------------------------------------------------------
__global__ void combine_kernel(const float* __restrict__ Ws,
                               const float* __restrict__ Wa,
                               const float* __restrict__ Wd,
                               const float* __restrict__ WC,
                               const float* __restrict__ bias,
                               const float* __restrict__ WCb) {
    int j = threadIdx.x;      // output col n
    int r = blockIdx.x;       // row k of fused M, or 384 = bias
    if (r < D_OUT) {
        int part = r >> 7;
        int i = r & 127;
        const float* W = (part == 0) ? Ws : ((part == 1) ? Wa : Wd);
        float acc = 0.f;
#pragma unroll 4
        for (int o = 0; o < 128; o++)
            acc += __ldg(&W[i * 128 + o]) * WC[(part * 128 + o) * D_OUT + j];
        __nv_bfloat16 hi = __float2bfloat16(acc);
        __nv_bfloat16 lo = __float2bfloat16(acc - __bfloat162float(hi));
        g_Bt[j * KP + r] = hi;
        g_Bt[j * KP + 384 + r] = lo;
    } else {
        float acc = WCb[j];
        for (int i = 0; i < D_OUT; i++)
            acc += bias[i] * WC[i * D_OUT + j];
        g_c[j] = acc;
    }
}

// ---------------------------------------------------------------------------
// Kernel 2: aggregation -> bf16 hi|lo rows of g_Xs; zero g_ss.
// ---------------------------------------------------------------------------
__global__ __launch_bounds__(128) void agg_kernel(const int* __restrict__ uniq,
                                                  const int* __restrict__ adj,
                                                  const int* __restrict__ dis,
                                                  const float* __restrict__ feat) {
    int n = blockIdx.x;
    int d = threadIdx.x;
    __shared__ int s_adj[K_NB];
    __shared__ int s_dis[K_NB];
    __shared__ int s_u;
    if (d < K_NB)            s_adj[d] = adj[n * K_NB + d];
    else if (d < 2 * K_NB)   s_dis[d - K_NB] = dis[n * K_NB + (d - K_NB)];
    else if (d == 64)        s_u = uniq[n];
    else if (d == 96)        g_ss[n] = 0.f;
    __syncthreads();

    float a = 0.f, b = 0.f;
#pragma unroll 8
    for (int k = 0; k < K_NB; k++)
        a += __ldg(&feat[(long)s_adj[k] * D_IN + d]);
#pragma unroll 8
    for (int k = 0; k < K_NB; k++)
        b += __ldg(&feat[(long)s_dis[k] * D_IN + d]);
    float sf = __ldg(&feat[(long)s_u * D_IN + d]);
    a *= (1.f / 32.f);
    b *= (1.f / 32.f);

    __nv_bfloat16* row = &g_Xs[(size_t)n * KP];
    __nv_bfloat16 h0 = __float2bfloat16(sf);
    __nv_bfloat16 h1 = __float2bfloat16(a);
    __nv_bfloat16 h2 = __float2bfloat16(b);
    row[d]       = h0;
    row[128 + d] = h1;
    row[256 + d] = h2;
    row[384 + d] = __float2bfloat16(sf - __bfloat162float(h0));
    row[512 + d] = __float2bfloat16(a  - __bfloat162float(h1));
    row[640 + d] = __float2bfloat16(b  - __bfloat162float(h2));
}

// ---------------------------------------------------------------------------
// Kernel 3: HMMA GEMM (mma.sync m16n8k16 bf16). Grid (157, 3).
// CTA: 128 rows x 128 cols, 8 warps (4x2), warp tile m32 x n64, BK=32,
// double-buffered smem, padded 80B row stride (conflict-free ldmatrix).
// 3 split segments: (Ah,Bh),(Al,Bh),(Ah,Bl) accumulated in registers.
// Epilogue: +bias, leakyReLU, store fp32 g_Z, rowwise sum(z^2) -> g_ss.
// ---------------------------------------------------------------------------
#define LDROW 80   // bytes per smem row (64B data + 16B pad)

__global__ __launch_bounds__(256) void gemm_hmma(int Mrows) {
    __shared__ __align__(128) char sA[2][128 * LDROW];
    __shared__ __align__(128) char sB[2][128 * LDROW];

    const int tid   = threadIdx.x;
    const int lane  = tid & 31;
    const int wid   = tid >> 5;
    const int warpM = wid & 3;     // 0..3
    const int warpN = wid >> 2;    // 0..1
    const int row0  = blockIdx.x * 128;
    const int n0    = blockIdx.y * 128;

    const uint32_t sA0 = smem_u32(&sA[0][0]);
    const uint32_t sB0 = smem_u32(&sB[0][0]);

    float acc[2][8][4];
#pragma unroll
    for (int mt = 0; mt < 2; mt++)
#pragma unroll
        for (int nt = 0; nt < 8; nt++)
#pragma unroll
            for (int q = 0; q < 4; q++) acc[mt][nt][q] = 0.f;

    // global->reg staging: 512 uint4 per tile per operand, 2 per thread
    const int ldr = tid >> 2;   // 0..63
    const int ldu = tid & 3;    // 0..3
    uint4 ga[2], gb[2];

    auto fetch = [&](int c) {
        int seg = c / 12, i = c % 12;
        int abase = ((seg == 1) ? 384 : 0) + i * 32;
        int bbase = ((seg == 2) ? 384 : 0) + i * 32;
#pragma unroll
        for (int it = 0; it < 2; it++) {
            int r = ldr + it * 64;
            ga[it] = *reinterpret_cast<const uint4*>(&g_Xs[(size_t)(row0 + r) * KP + abase + ldu * 8]);
            gb[it] = *reinterpret_cast<const uint4*>(&g_Bt[(size_t)(n0 + r) * KP + bbase + ldu * 8]);
        }
    };
    auto stage = [&](int buf) {
#pragma unroll
        for (int it = 0; it < 2; it++) {
            int r = ldr + it * 64;
            *reinterpret_cast<uint4*>(&sA[buf][r * LDROW + ldu * 16]) = ga[it];
            *reinterpret_cast<uint4*>(&sB[buf][r * LDROW + ldu * 16]) = gb[it];
        }
    };

    // ldmatrix lane routing
    const int lq = lane >> 3, lr = lane & 7;
    // A x4 tiles: m_off=(q&1)*8, k_off=(q>>1)*8  -> regs a0..a3
    const int a_mrow = warpM * 32 + (lq & 1) * 8 + lr;
    const int a_koff = (lq >> 1) * 8;
    // B x4 tiles: n_off=(q>>1)*8, k_off=(q&1)*8 -> regs: nt even b0,b1 | nt odd b0,b1
    const int b_nrow = warpN * 64 + (lq >> 1) * 8 + lr;
    const int b_koff = (lq & 1) * 8;

    fetch(0);
    stage(0);
    __syncthreads();

    for (int c = 0; c < NCHUNK; c++) {
        const int buf = c & 1;
        if (c + 1 < NCHUNK) fetch(c + 1);

        const uint32_t abuf = sA0 + buf * (128 * LDROW);
        const uint32_t bbuf = sB0 + buf * (128 * LDROW);
#pragma unroll
        for (int ks = 0; ks < 2; ks++) {
            uint32_t a[2][4];
#pragma unroll
            for (int mt = 0; mt < 2; mt++) {
                uint32_t addr = abuf + (a_mrow + mt * 16) * LDROW + (ks * 16 + a_koff) * 2;
                LDMATRIX_X4(a[mt][0], a[mt][1], a[mt][2], a[mt][3], addr);
            }
            uint32_t b[4][4];
#pragma unroll
            for (int np = 0; np < 4; np++) {
                uint32_t addr = bbuf + (b_nrow + np * 16) * LDROW + (ks * 16 + b_koff) * 2;
                LDMATRIX_X4(b[np][0], b[np][1], b[np][2], b[np][3], addr);
            }
#pragma unroll
            for (int mt = 0; mt < 2; mt++)
#pragma unroll
                for (int np = 0; np < 4; np++) {
                    MMA_16816(acc[mt][np * 2 + 0], a[mt], b[np][0], b[np][1]);
                    MMA_16816(acc[mt][np * 2 + 1], a[mt], b[np][2], b[np][3]);
                }
        }
        if (c + 1 < NCHUNK) {
            stage(buf ^ 1);
            __syncthreads();
        }
    }

    // ---- epilogue ----
    const int g = lane >> 2;   // row within m16 tile
    const int cq = lane & 3;   // col quad
#pragma unroll
    for (int mt = 0; mt < 2; mt++) {
        const int rbase = row0 + warpM * 32 + mt * 16;
        float ss0 = 0.f, ss1 = 0.f;
#pragma unroll
        for (int nt = 0; nt < 8; nt++) {
            int col = n0 + warpN * 64 + nt * 8 + cq * 2;
            float b0 = __ldg(&g_c[col]);
            float b1 = __ldg(&g_c[col + 1]);
            float z0 = acc[mt][nt][0] + b0; z0 = (z0 >= 0.f) ? z0 : 0.2f * z0;
            float z1 = acc[mt][nt][1] + b1; z1 = (z1 >= 0.f) ? z1 : 0.2f * z1;
            float z2 = acc[mt][nt][2] + b0; z2 = (z2 >= 0.f) ? z2 : 0.2f * z2;
            float z3 = acc[mt][nt][3] + b1; z3 = (z3 >= 0.f) ? z3 : 0.2f * z3;
            *reinterpret_cast<float2*>(&g_Z[(size_t)(rbase + g) * D_OUT + col])     = make_float2(z0, z1);
            *reinterpret_cast<float2*>(&g_Z[(size_t)(rbase + g + 8) * D_OUT + col]) = make_float2(z2, z3);
            ss0 += z0 * z0 + z1 * z1;
            ss1 += z2 * z2 + z3 * z3;
        }
        ss0 += __shfl_xor_sync(0xffffffffu, ss0, 1);
        ss0 += __shfl_xor_sync(0xffffffffu, ss0, 2);
        ss1 += __shfl_xor_sync(0xffffffffu, ss1, 1);
        ss1 += __shfl_xor_sync(0xffffffffu, ss1, 2);
        if (cq == 0) {
            atomicAdd(&g_ss[rbase + g], ss0);
            atomicAdd(&g_ss[rbase + g + 8], ss1);
        }
    }
}

// ---------------------------------------------------------------------------
// Kernel 4: out[b] = Z[idx[b]] / max(||Z[idx[b]]||, 1e-12). 4 rows per block.
// ---------------------------------------------------------------------------
__global__ __launch_bounds__(384) void gather_kernel(const int* __restrict__ nidx,
                                                     float* __restrict__ out) {
    int t = threadIdx.x;
    int b = blockIdx.x * 4 + t / 96;
    int u = t % 96;
    int idx = __ldg(&nidx[b]);
    float s = __ldg(&g_ss[idx]);
    float inv = 1.f / fmaxf(sqrtf(s), 1e-12f);
    float4 v = *reinterpret_cast<const float4*>(&g_Z[(size_t)idx * D_OUT + u * 4]);
    v.x *= inv; v.y *= inv; v.z *= inv; v.w *= inv;
    *reinterpret_cast<float4*>(&out[(size_t)b * D_OUT + u * 4]) = v;
}

// ---------------------------------------------------------------------------
extern "C" void kernel_launch(void* const* d_in, const int* in_sizes, int n_in,
                              void* d_out, int out_size) {
    const int*   uniq = (const int*)d_in[0];
    const int*   adj  = (const int*)d_in[1];
    const int*   dis  = (const int*)d_in[2];
    const int*   nidx = (const int*)d_in[3];
    const float* feat = (const float*)d_in[4];
    const float* Ws   = (const float*)d_in[5];
    const float* Wa   = (const float*)d_in[6];
    const float* Wd   = (const float*)d_in[7];
    const float* bias = (const float*)d_in[8];
    const float* WC   = (const float*)d_in[9];
    const float* WCb  = (const float*)d_in[10];
    float* out = (float*)d_out;

    combine_kernel<<<D_OUT + 1, D_OUT>>>(Ws, Wa, Wd, WC, bias, WCb);
    agg_kernel<<<N_UNIQ, 128>>>(uniq, adj, dis, feat);
    gemm_hmma<<<dim3(N_CTAS_M, 3), 256>>>(N_UNIQ);
    gather_kernel<<<B_OUT / 4, 384>>>(nidx, out);
}

// round 4
// speedup vs baseline: 1.9593x; 1.3674x over previous
#include <cuda_runtime.h>
#include <cuda_bf16.h>
#include <math.h>
#include <stdint.h>

#define N_UNIQ 20000
#define D_IN   128
#define D_OUT  384
#define K_NB   32
#define B_OUT  40000

#define KP        768          // split-K storage: [hi 384 | lo 384]
#define ROWS_PAD  20096        // 157 * 128
#define N_CTAS_M  157
#define NCHUNK    36           // 3 segments x 12 chunks of BK=32

// ---------------- scratch (__device__ globals; zero-init once) --------------
__device__ __align__(128) __nv_bfloat16 g_Xs[ROWS_PAD * KP];  // A, hi|lo
__device__ __align__(128) __nv_bfloat16 g_Bt[D_OUT * KP];     // B [n][k], hi|lo
__device__ __align__(128) float g_c[D_OUT];                   // fused bias
__device__ __align__(128) float g_Z[ROWS_PAD * D_OUT];        // unnormalized out
__device__ __align__(128) float g_ss[ROWS_PAD];               // per-row sum sq

// ---------------- helpers ----------------------------------------------------
__device__ __forceinline__ uint32_t smem_u32(const void* p) {
    uint32_t a;
    asm("{ .reg .u64 t; cvta.to.shared.u64 t, %1; cvt.u32.u64 %0, t; }" : "=r"(a) : "l"(p));
    return a;
}
#define LDMATRIX_X4(r0, r1, r2, r3, addr) \
    asm volatile("ldmatrix.sync.aligned.m8n8.x4.shared.b16 {%0,%1,%2,%3}, [%4];" \
                 : "=r"(r0), "=r"(r1), "=r"(r2), "=r"(r3) : "r"(addr))
#define MMA_16816(d, a, b0, b1) \
    asm volatile("mma.sync.aligned.m16n8k16.row.col.f32.bf16.bf16.f32 " \
                 "{%0,%1,%2,%3}, {%4,%5,%6,%7}, {%8,%9}, {%0,%1,%2,%3};" \
                 : "+f"((d)[0]), "+f"((d)[1]), "+f"((d)[2]), "+f"((d)[3]) \
                 : "r"((a)[0]), "r"((a)[1]), "r"((a)[2]), "r"((a)[3]), \
                   "r"(b0), "r"(b1))

// ---------------------------------------------------------------------------
// Kernel 1: fused weight (transposed [n][k], bf16 hi|lo split) + fused bias.
// ---------------------------------------------------------------------------
__global__ void combine_kernel(const float* __restrict__ Ws,
                               const float* __restrict__ Wa,
                               const float* __restrict__ Wd,
                               const float* __restrict__ WC,
                               const float* __restrict__ bias,
                               const float* __restrict__ WCb) {
    int j = threadIdx.x;      // output col n
    int r = blockIdx.x;       // row k of fused M, or 384 = bias
    if (r < D_OUT) {
        int part = r >> 7;
        int i = r & 127;
        const float* W = (part == 0) ? Ws : ((part == 1) ? Wa : Wd);
        float acc = 0.f;
#pragma unroll 4
        for (int o = 0; o < 128; o++)
            acc += __ldg(&W[i * 128 + o]) * WC[(part * 128 + o) * D_OUT + j];
        __nv_bfloat16 hi = __float2bfloat16(acc);
        __nv_bfloat16 lo = __float2bfloat16(acc - __bfloat162float(hi));
        g_Bt[j * KP + r] = hi;
        g_Bt[j * KP + 384 + r] = lo;
    } else {
        float acc = WCb[j];
        for (int i = 0; i < D_OUT; i++)
            acc += bias[i] * WC[i * D_OUT + j];
        g_c[j] = acc;
    }
}

// ---------------------------------------------------------------------------
// Kernel 2: aggregation, warp-per-node. Lane l owns cols 4l..4l+3 (float4).
// 64 independent float4 gathers per lane (full 512B row per warp per load).
// Indices kept in regs, broadcast via shfl. Writes bf16 hi|lo (8B per lane
// per segment). Also zeroes g_ss.
// ---------------------------------------------------------------------------
__global__ __launch_bounds__(256) void agg_kernel(const int* __restrict__ uniq,
                                                  const int* __restrict__ adj,
                                                  const int* __restrict__ dis,
                                                  const float* __restrict__ feat) {
    const int warp = threadIdx.x >> 5;
    const int lane = threadIdx.x & 31;
    const int n = blockIdx.x * 8 + warp;

    const int ia = __ldg(&adj[n * K_NB + lane]);   // my adj index
    const int id = __ldg(&dis[n * K_NB + lane]);   // my dis index
    const int iu = __ldg(&uniq[n]);                // broadcast load (same addr)
    if (lane == 0) g_ss[n] = 0.f;

    const float4* f4 = reinterpret_cast<const float4*>(feat);

    float4 a = make_float4(0.f, 0.f, 0.f, 0.f);
    float4 b = make_float4(0.f, 0.f, 0.f, 0.f);
#pragma unroll
    for (int k = 0; k < K_NB; k++) {
        int ra = __shfl_sync(0xffffffffu, ia, k);
        float4 v = __ldg(&f4[(size_t)ra * 32 + lane]);
        a.x += v.x; a.y += v.y; a.z += v.z; a.w += v.w;
    }
#pragma unroll
    for (int k = 0; k < K_NB; k++) {
        int rd = __shfl_sync(0xffffffffu, id, k);
        float4 v = __ldg(&f4[(size_t)rd * 32 + lane]);
        b.x += v.x; b.y += v.y; b.z += v.z; b.w += v.w;
    }
    float4 sf = __ldg(&f4[(size_t)iu * 32 + lane]);
    const float inv = 1.f / 32.f;
    a.x *= inv; a.y *= inv; a.z *= inv; a.w *= inv;
    b.x *= inv; b.y *= inv; b.z *= inv; b.w *= inv;

    __nv_bfloat16* row = &g_Xs[(size_t)n * KP];
    // pack 4 floats -> 4 bf16 (8B) hi, and lo
    auto store_seg = [&](int base, float4 v) {
        __nv_bfloat16 h[4], l[4];
        float vv[4] = {v.x, v.y, v.z, v.w};
#pragma unroll
        for (int q = 0; q < 4; q++) {
            h[q] = __float2bfloat16(vv[q]);
            l[q] = __float2bfloat16(vv[q] - __bfloat162float(h[q]));
        }
        *reinterpret_cast<uint2*>(&row[base + lane * 4])       = *reinterpret_cast<uint2*>(h);
        *reinterpret_cast<uint2*>(&row[384 + base + lane * 4]) = *reinterpret_cast<uint2*>(l);
    };
    store_seg(0, sf);
    store_seg(128, a);
    store_seg(256, b);
}

// ---------------------------------------------------------------------------
// Kernel 3: HMMA GEMM (mma.sync m16n8k16 bf16). Grid (157, 3).
// CTA: 128 rows x 128 cols, 8 warps (4x2), warp tile m32 x n64, BK=32,
// double-buffered smem, padded 80B row stride (conflict-free ldmatrix).
// 3 split segments: (Ah,Bh),(Al,Bh),(Ah,Bl) accumulated in registers.
// ---------------------------------------------------------------------------
#define LDROW 80   // bytes per smem row (64B data + 16B pad)

__global__ __launch_bounds__(256) void gemm_hmma(int Mrows) {
    __shared__ __align__(128) char sA[2][128 * LDROW];
    __shared__ __align__(128) char sB[2][128 * LDROW];

    const int tid   = threadIdx.x;
    const int lane  = tid & 31;
    const int wid   = tid >> 5;
    const int warpM = wid & 3;     // 0..3
    const int warpN = wid >> 2;    // 0..1
    const int row0  = blockIdx.x * 128;
    const int n0    = blockIdx.y * 128;

    const uint32_t sA0 = smem_u32(&sA[0][0]);
    const uint32_t sB0 = smem_u32(&sB[0][0]);

    float acc[2][8][4];
#pragma unroll
    for (int mt = 0; mt < 2; mt++)
#pragma unroll
        for (int nt = 0; nt < 8; nt++)
#pragma unroll
            for (int q = 0; q < 4; q++) acc[mt][nt][q] = 0.f;

    const int ldr = tid >> 2;   // 0..63
    const int ldu = tid & 3;    // 0..3
    uint4 ga[2], gb[2];

    auto fetch = [&](int c) {
        int seg = c / 12, i = c % 12;
        int abase = ((seg == 1) ? 384 : 0) + i * 32;
        int bbase = ((seg == 2) ? 384 : 0) + i * 32;
#pragma unroll
        for (int it = 0; it < 2; it++) {
            int r = ldr + it * 64;
            ga[it] = *reinterpret_cast<const uint4*>(&g_Xs[(size_t)(row0 + r) * KP + abase + ldu * 8]);
            gb[it] = *reinterpret_cast<const uint4*>(&g_Bt[(size_t)(n0 + r) * KP + bbase + ldu * 8]);
        }
    };
    auto stage = [&](int buf) {
#pragma unroll
        for (int it = 0; it < 2; it++) {
            int r = ldr + it * 64;
            *reinterpret_cast<uint4*>(&sA[buf][r * LDROW + ldu * 16]) = ga[it];
            *reinterpret_cast<uint4*>(&sB[buf][r * LDROW + ldu * 16]) = gb[it];
        }
    };

    const int lq = lane >> 3, lr = lane & 7;
    const int a_mrow = warpM * 32 + (lq & 1) * 8 + lr;
    const int a_koff = (lq >> 1) * 8;
    const int b_nrow = warpN * 64 + (lq >> 1) * 8 + lr;
    const int b_koff = (lq & 1) * 8;

    fetch(0);
    stage(0);
    __syncthreads();

    for (int c = 0; c < NCHUNK; c++) {
        const int buf = c & 1;
        if (c + 1 < NCHUNK) fetch(c + 1);

        const uint32_t abuf = sA0 + buf * (128 * LDROW);
        const uint32_t bbuf = sB0 + buf * (128 * LDROW);
#pragma unroll
        for (int ks = 0; ks < 2; ks++) {
            uint32_t a[2][4];
#pragma unroll
            for (int mt = 0; mt < 2; mt++) {
                uint32_t addr = abuf + (a_mrow + mt * 16) * LDROW + (ks * 16 + a_koff) * 2;
                LDMATRIX_X4(a[mt][0], a[mt][1], a[mt][2], a[mt][3], addr);
            }
            uint32_t b[4][4];
#pragma unroll
            for (int np = 0; np < 4; np++) {
                uint32_t addr = bbuf + (b_nrow + np * 16) * LDROW + (ks * 16 + b_koff) * 2;
                LDMATRIX_X4(b[np][0], b[np][1], b[np][2], b[np][3], addr);
            }
#pragma unroll
            for (int mt = 0; mt < 2; mt++)
#pragma unroll
                for (int np = 0; np < 4; np++) {
                    MMA_16816(acc[mt][np * 2 + 0], a[mt], b[np][0], b[np][1]);
                    MMA_16816(acc[mt][np * 2 + 1], a[mt], b[np][2], b[np][3]);
                }
        }
        if (c + 1 < NCHUNK) {
            stage(buf ^ 1);
            __syncthreads();
        }
    }

    // ---- epilogue ----
    const int g = lane >> 2;   // row within m16 tile
    const int cq = lane & 3;   // col quad
#pragma unroll
    for (int mt = 0; mt < 2; mt++) {
        const int rbase = row0 + warpM * 32 + mt * 16;
        float ss0 = 0.f, ss1 = 0.f;
#pragma unroll
        for (int nt = 0; nt < 8; nt++) {
            int col = n0 + warpN * 64 + nt * 8 + cq * 2;
            float b0 = __ldg(&g_c[col]);
            float b1 = __ldg(&g_c[col + 1]);
            float z0 = acc[mt][nt][0] + b0; z0 = (z0 >= 0.f) ? z0 : 0.2f * z0;
            float z1 = acc[mt][nt][1] + b1; z1 = (z1 >= 0.f) ? z1 : 0.2f * z1;
            float z2 = acc[mt][nt][2] + b0; z2 = (z2 >= 0.f) ? z2 : 0.2f * z2;
            float z3 = acc[mt][nt][3] + b1; z3 = (z3 >= 0.f) ? z3 : 0.2f * z3;
            *reinterpret_cast<float2*>(&g_Z[(size_t)(rbase + g) * D_OUT + col])     = make_float2(z0, z1);
            *reinterpret_cast<float2*>(&g_Z[(size_t)(rbase + g + 8) * D_OUT + col]) = make_float2(z2, z3);
            ss0 += z0 * z0 + z1 * z1;
            ss1 += z2 * z2 + z3 * z3;
        }
        ss0 += __shfl_xor_sync(0xffffffffu, ss0, 1);
        ss0 += __shfl_xor_sync(0xffffffffu, ss0, 2);
        ss1 += __shfl_xor_sync(0xffffffffu, ss1, 1);
        ss1 += __shfl_xor_sync(0xffffffffu, ss1, 2);
        if (cq == 0) {
            atomicAdd(&g_ss[rbase + g], ss0);
            atomicAdd(&g_ss[rbase + g + 8], ss1);
        }
    }
}

// ---------------------------------------------------------------------------
// Kernel 4: normalize + batch gather. Warp per output row, lane handles 3
// float4s (MLP 3). 8 rows per 256-thread block, grid 5000.
// ---------------------------------------------------------------------------
__global__ __launch_bounds__(256) void gather_kernel(const int* __restrict__ nidx,
                                                     float* __restrict__ out) {
    const int warp = threadIdx.x >> 5;
    const int lane = threadIdx.x & 31;
    const int b = blockIdx.x * 8 + warp;
    const int idx = __ldg(&nidx[b]);
    const float s = __ldg(&g_ss[idx]);
    const float inv = 1.f / fmaxf(sqrtf(s), 1e-12f);

    const float4* zp = reinterpret_cast<const float4*>(&g_Z[(size_t)idx * D_OUT]);
    float4* op = reinterpret_cast<float4*>(&out[(size_t)b * D_OUT]);
    float4 v0 = __ldg(&zp[lane]);
    float4 v1 = __ldg(&zp[lane + 32]);
    float4 v2 = __ldg(&zp[lane + 64]);
    v0.x *= inv; v0.y *= inv; v0.z *= inv; v0.w *= inv;
    v1.x *= inv; v1.y *= inv; v1.z *= inv; v1.w *= inv;
    v2.x *= inv; v2.y *= inv; v2.z *= inv; v2.w *= inv;
    op[lane]      = v0;
    op[lane + 32] = v1;
    op[lane + 64] = v2;
}

// ---------------------------------------------------------------------------
extern "C" void kernel_launch(void* const* d_in, const int* in_sizes, int n_in,
                              void* d_out, int out_size) {
    const int*   uniq = (const int*)d_in[0];
    const int*   adj  = (const int*)d_in[1];
    const int*   dis  = (const int*)d_in[2];
    const int*   nidx = (const int*)d_in[3];
    const float* feat = (const float*)d_in[4];
    const float* Ws   = (const float*)d_in[5];
    const float* Wa   = (const float*)d_in[6];
    const float* Wd   = (const float*)d_in[7];
    const float* bias = (const float*)d_in[8];
    const float* WC   = (const float*)d_in[9];
    const float* WCb  = (const float*)d_in[10];
    float* out = (float*)d_out;

    combine_kernel<<<D_OUT + 1, D_OUT>>>(Ws, Wa, Wd, WC, bias, WCb);
    agg_kernel<<<N_UNIQ / 8, 256>>>(uniq, adj, dis, feat);
    gemm_hmma<<<dim3(N_CTAS_M, 3), 256>>>(N_UNIQ);
    gather_kernel<<<B_OUT / 8, 256>>>(nidx, out);
}

// round 5
// speedup vs baseline: 2.0020x; 1.0218x over previous
#include <cuda_runtime.h>
#include <cuda_bf16.h>
#include <math.h>
#include <stdint.h>

#define N_UNIQ 20000
#define D_IN   128
#define D_OUT  384
#define K_NB   32
#define B_OUT  40000

#define KP        768          // split-K storage: [hi 384 | lo 384]
#define ROWS_PAD  20096        // 157 * 128
#define N_CTAS_M  157
#define NCHUNK    36           // 3 segments x 12 chunks of BK=32

// ---------------- scratch (__device__ globals) ------------------------------
__device__ __align__(128) __nv_bfloat16 g_Xs[ROWS_PAD * KP];  // A, hi|lo
__device__ __align__(128) __nv_bfloat16 g_Bt[D_OUT * KP];     // B [n][k], hi|lo
__device__ __align__(128) float g_c[D_OUT];                   // fused bias
__device__ __align__(128) float g_Z[ROWS_PAD * D_OUT];        // unnormalized out
__device__ __align__(128) float g_ssp[3 * ROWS_PAD];          // per-(yslab,row) sum sq

// ---------------- helpers ----------------------------------------------------
__device__ __forceinline__ uint32_t smem_u32(const void* p) {
    uint32_t a;
    asm("{ .reg .u64 t; cvta.to.shared.u64 t, %1; cvt.u32.u64 %0, t; }" : "=r"(a) : "l"(p));
    return a;
}
#define LDMATRIX_X4(r0, r1, r2, r3, addr) \
    asm volatile("ldmatrix.sync.aligned.m8n8.x4.shared.b16 {%0,%1,%2,%3}, [%4];" \
                 : "=r"(r0), "=r"(r1), "=r"(r2), "=r"(r3) : "r"(addr))
#define MMA_16816(d, a, b0, b1) \
    asm volatile("mma.sync.aligned.m16n8k16.row.col.f32.bf16.bf16.f32 " \
                 "{%0,%1,%2,%3}, {%4,%5,%6,%7}, {%8,%9}, {%0,%1,%2,%3};" \
                 : "+f"((d)[0]), "+f"((d)[1]), "+f"((d)[2]), "+f"((d)[3]) \
                 : "r"((a)[0]), "r"((a)[1]), "r"((a)[2]), "r"((a)[3]), \
                   "r"(b0), "r"(b1))
#define CP_ASYNC_16(dst, src) \
    asm volatile("cp.async.cg.shared.global [%0], [%1], 16;" :: "r"(dst), "l"(src))
#define CP_COMMIT() asm volatile("cp.async.commit_group;" ::: "memory")
#define CP_WAIT2()  asm volatile("cp.async.wait_group 2;" ::: "memory")

// ---------------------------------------------------------------------------
// Kernel 1: fused weight (transposed [n][k], bf16 hi|lo split) + fused bias.
// 48 blocks x 8 M-rows: W rows staged in smem, each WC element reused 8x.
// ---------------------------------------------------------------------------
__global__ __launch_bounds__(384) void combine_kernel(const float* __restrict__ Ws,
                               const float* __restrict__ Wa,
                               const float* __restrict__ Wd,
                               const float* __restrict__ WC,
                               const float* __restrict__ bias,
                               const float* __restrict__ WCb) {
    int j = threadIdx.x;      // output col n (0..383)
    int rb = blockIdx.x;      // 0..47 = 8-row groups, 48 = bias
    if (rb < 48) {
        int r0 = rb * 8;
        int part = r0 >> 7;
        const float* W = (part == 0) ? Ws : ((part == 1) ? Wa : Wd);
        __shared__ float sW[8][128];
        for (int t = j; t < 1024; t += 384) {
            int q = t >> 7, o = t & 127;
            sW[q][o] = W[((r0 & 127) + q) * 128 + o];
        }
        __syncthreads();
        float acc[8] = {0.f, 0.f, 0.f, 0.f, 0.f, 0.f, 0.f, 0.f};
#pragma unroll 4
        for (int o = 0; o < 128; o++) {
            float wc = __ldg(&WC[(part * 128 + o) * D_OUT + j]);
#pragma unroll
            for (int q = 0; q < 8; q++) acc[q] += sW[q][o] * wc;
        }
#pragma unroll
        for (int q = 0; q < 8; q++) {
            __nv_bfloat16 hi = __float2bfloat16(acc[q]);
            __nv_bfloat16 lo = __float2bfloat16(acc[q] - __bfloat162float(hi));
            g_Bt[j * KP + r0 + q] = hi;
            g_Bt[j * KP + 384 + r0 + q] = lo;
        }
    } else {
        float acc = WCb[j];
        for (int i = 0; i < D_OUT; i++)
            acc += bias[i] * WC[i * D_OUT + j];
        g_c[j] = acc;
    }
}

// ---------------------------------------------------------------------------
// Kernel 2: aggregation, warp-per-node (float4 per lane, indices via shfl).
// ---------------------------------------------------------------------------
__global__ __launch_bounds__(256) void agg_kernel(const int* __restrict__ uniq,
                                                  const int* __restrict__ adj,
                                                  const int* __restrict__ dis,
                                                  const float* __restrict__ feat) {
    const int warp = threadIdx.x >> 5;
    const int lane = threadIdx.x & 31;
    const int n = blockIdx.x * 8 + warp;

    const int ia = __ldg(&adj[n * K_NB + lane]);
    const int id = __ldg(&dis[n * K_NB + lane]);
    const int iu = __ldg(&uniq[n]);

    const float4* f4 = reinterpret_cast<const float4*>(feat);

    float4 a = make_float4(0.f, 0.f, 0.f, 0.f);
    float4 b = make_float4(0.f, 0.f, 0.f, 0.f);
#pragma unroll
    for (int k = 0; k < K_NB; k++) {
        int ra = __shfl_sync(0xffffffffu, ia, k);
        float4 v = __ldg(&f4[(size_t)ra * 32 + lane]);
        a.x += v.x; a.y += v.y; a.z += v.z; a.w += v.w;
    }
#pragma unroll
    for (int k = 0; k < K_NB; k++) {
        int rd = __shfl_sync(0xffffffffu, id, k);
        float4 v = __ldg(&f4[(size_t)rd * 32 + lane]);
        b.x += v.x; b.y += v.y; b.z += v.z; b.w += v.w;
    }
    float4 sf = __ldg(&f4[(size_t)iu * 32 + lane]);
    const float inv = 1.f / 32.f;
    a.x *= inv; a.y *= inv; a.z *= inv; a.w *= inv;
    b.x *= inv; b.y *= inv; b.z *= inv; b.w *= inv;

    __nv_bfloat16* row = &g_Xs[(size_t)n * KP];
    auto store_seg = [&](int base, float4 v) {
        __nv_bfloat16 h[4], l[4];
        float vv[4] = {v.x, v.y, v.z, v.w};
#pragma unroll
        for (int q = 0; q < 4; q++) {
            h[q] = __float2bfloat16(vv[q]);
            l[q] = __float2bfloat16(vv[q] - __bfloat162float(h[q]));
        }
        *reinterpret_cast<uint2*>(&row[base + lane * 4])       = *reinterpret_cast<uint2*>(h);
        *reinterpret_cast<uint2*>(&row[384 + base + lane * 4]) = *reinterpret_cast<uint2*>(l);
    };
    store_seg(0, sf);
    store_seg(128, a);
    store_seg(256, b);
}

// ---------------------------------------------------------------------------
// Kernel 3: HMMA GEMM, 4-stage cp.async pipeline. Grid (157, 3), 2 CTAs/SM.
// CTA 128x128, 8 warps (4Mx2N) m32xn64 each, BK=32, LDROW=80 (conflict-free).
// 3 split segments (Ah,Bh),(Al,Bh),(Ah,Bl) accumulate in registers.
// Epilogue: +bias, leakyReLU, g_Z store, smem-reduced row sumsq -> g_ssp.
// ---------------------------------------------------------------------------
#define LDROW   80
#define STG     (128 * LDROW)     // 10240 B per operand stage
#define SMEM_GEMM (4 * 2 * STG)   // 81920

__global__ __launch_bounds__(256, 2) void gemm_hmma(int Mrows) {
    extern __shared__ __align__(128) char dsm[];
    const uint32_t sbase = smem_u32(dsm);
    const uint32_t aarea = sbase;
    const uint32_t barea = sbase + 4 * STG;

    const int tid   = threadIdx.x;
    const int lane  = tid & 31;
    const int wid   = tid >> 5;
    const int warpM = wid & 3;
    const int warpN = wid >> 2;
    const int row0  = blockIdx.x * 128;
    const int n0    = blockIdx.y * 128;

    float acc[2][8][4];
#pragma unroll
    for (int mt = 0; mt < 2; mt++)
#pragma unroll
        for (int nt = 0; nt < 8; nt++)
#pragma unroll
            for (int q = 0; q < 4; q++) acc[mt][nt][q] = 0.f;

    const int ldr = tid >> 2;   // 0..63
    const int ldu = tid & 3;    // 0..3

    auto issue_stage = [&](int c) {
        int s = c & 3;
        int seg = c / 12, i = c % 12;
        int abase = ((seg == 1) ? 384 : 0) + i * 32;
        int bbase = ((seg == 2) ? 384 : 0) + i * 32;
        uint32_t da = aarea + s * STG;
        uint32_t db = barea + s * STG;
#pragma unroll
        for (int it = 0; it < 2; it++) {
            int r = ldr + it * 64;
            CP_ASYNC_16(da + r * LDROW + ldu * 16,
                        (const void*)&g_Xs[(size_t)(row0 + r) * KP + abase + ldu * 8]);
            CP_ASYNC_16(db + r * LDROW + ldu * 16,
                        (const void*)&g_Bt[(size_t)(n0 + r) * KP + bbase + ldu * 8]);
        }
    };

    const int lq = lane >> 3, lr = lane & 7;
    const int a_mrow = warpM * 32 + (lq & 1) * 8 + lr;
    const int a_koff = (lq >> 1) * 8;
    const int b_nrow = warpN * 64 + (lq >> 1) * 8 + lr;
    const int b_koff = (lq & 1) * 8;

    // prologue: stages 0..2 in flight
#pragma unroll
    for (int s = 0; s < 3; s++) { issue_stage(s); CP_COMMIT(); }

    for (int c = 0; c < NCHUNK; c++) {
        CP_WAIT2();
        __syncthreads();
        if (c + 3 < NCHUNK) issue_stage(c + 3);
        CP_COMMIT();

        const int s = c & 3;
        const uint32_t abuf = aarea + s * STG;
        const uint32_t bbuf = barea + s * STG;
#pragma unroll
        for (int ks = 0; ks < 2; ks++) {
            uint32_t a[2][4];
#pragma unroll
            for (int mt = 0; mt < 2; mt++) {
                uint32_t addr = abuf + (a_mrow + mt * 16) * LDROW + (ks * 16 + a_koff) * 2;
                LDMATRIX_X4(a[mt][0], a[mt][1], a[mt][2], a[mt][3], addr);
            }
            uint32_t b[4][4];
#pragma unroll
            for (int np = 0; np < 4; np++) {
                uint32_t addr = bbuf + (b_nrow + np * 16) * LDROW + (ks * 16 + b_koff) * 2;
                LDMATRIX_X4(b[np][0], b[np][1], b[np][2], b[np][3], addr);
            }
#pragma unroll
            for (int mt = 0; mt < 2; mt++)
#pragma unroll
                for (int np = 0; np < 4; np++) {
                    MMA_16816(acc[mt][np * 2 + 0], a[mt], b[np][0], b[np][1]);
                    MMA_16816(acc[mt][np * 2 + 1], a[mt], b[np][2], b[np][3]);
                }
        }
    }

    // ---- epilogue ----
    const int g  = lane >> 2;   // row within m16 tile
    const int cq = lane & 3;    // col quad
    float ssA[2], ssB[2];
#pragma unroll
    for (int mt = 0; mt < 2; mt++) {
        const int rbase = row0 + warpM * 32 + mt * 16;
        float ss0 = 0.f, ss1 = 0.f;
#pragma unroll
        for (int nt = 0; nt < 8; nt++) {
            int col = n0 + warpN * 64 + nt * 8 + cq * 2;
            float b0 = __ldg(&g_c[col]);
            float b1 = __ldg(&g_c[col + 1]);
            float z0 = acc[mt][nt][0] + b0; z0 = (z0 >= 0.f) ? z0 : 0.2f * z0;
            float z1 = acc[mt][nt][1] + b1; z1 = (z1 >= 0.f) ? z1 : 0.2f * z1;
            float z2 = acc[mt][nt][2] + b0; z2 = (z2 >= 0.f) ? z2 : 0.2f * z2;
            float z3 = acc[mt][nt][3] + b1; z3 = (z3 >= 0.f) ? z3 : 0.2f * z3;
            *reinterpret_cast<float2*>(&g_Z[(size_t)(rbase + g) * D_OUT + col])     = make_float2(z0, z1);
            *reinterpret_cast<float2*>(&g_Z[(size_t)(rbase + g + 8) * D_OUT + col]) = make_float2(z2, z3);
            ss0 += z0 * z0 + z1 * z1;
            ss1 += z2 * z2 + z3 * z3;
        }
        ss0 += __shfl_xor_sync(0xffffffffu, ss0, 1);
        ss0 += __shfl_xor_sync(0xffffffffu, ss0, 2);
        ss1 += __shfl_xor_sync(0xffffffffu, ss1, 1);
        ss1 += __shfl_xor_sync(0xffffffffu, ss1, 2);
        ssA[mt] = ss0;
        ssB[mt] = ss1;
    }
    __syncthreads();
    float* s_ss = reinterpret_cast<float*>(dsm);
    if (tid < 128) s_ss[tid] = 0.f;
    __syncthreads();
    if (cq == 0) {
#pragma unroll
        for (int mt = 0; mt < 2; mt++) {
            atomicAdd(&s_ss[warpM * 32 + mt * 16 + g],     ssA[mt]);
            atomicAdd(&s_ss[warpM * 32 + mt * 16 + 8 + g], ssB[mt]);
        }
    }
    __syncthreads();
    if (tid < 128) g_ssp[(size_t)blockIdx.y * ROWS_PAD + row0 + tid] = s_ss[tid];
}

// ---------------------------------------------------------------------------
// Kernel 4: normalize + batch gather. Warp per output row, MLP 3.
// ---------------------------------------------------------------------------
__global__ __launch_bounds__(256) void gather_kernel(const int* __restrict__ nidx,
                                                     float* __restrict__ out) {
    const int warp = threadIdx.x >> 5;
    const int lane = threadIdx.x & 31;
    const int b = blockIdx.x * 8 + warp;
    const int idx = __ldg(&nidx[b]);
    const float s = __ldg(&g_ssp[idx]) + __ldg(&g_ssp[ROWS_PAD + idx]) +
                    __ldg(&g_ssp[2 * ROWS_PAD + idx]);
    const float inv = 1.f / fmaxf(sqrtf(s), 1e-12f);

    const float4* zp = reinterpret_cast<const float4*>(&g_Z[(size_t)idx * D_OUT]);
    float4* op = reinterpret_cast<float4*>(&out[(size_t)b * D_OUT]);
    float4 v0 = __ldg(&zp[lane]);
    float4 v1 = __ldg(&zp[lane + 32]);
    float4 v2 = __ldg(&zp[lane + 64]);
    v0.x *= inv; v0.y *= inv; v0.z *= inv; v0.w *= inv;
    v1.x *= inv; v1.y *= inv; v1.z *= inv; v1.w *= inv;
    v2.x *= inv; v2.y *= inv; v2.z *= inv; v2.w *= inv;
    op[lane]      = v0;
    op[lane + 32] = v1;
    op[lane + 64] = v2;
}

// ---------------------------------------------------------------------------
extern "C" void kernel_launch(void* const* d_in, const int* in_sizes, int n_in,
                              void* d_out, int out_size) {
    const int*   uniq = (const int*)d_in[0];
    const int*   adj  = (const int*)d_in[1];
    const int*   dis  = (const int*)d_in[2];
    const int*   nidx = (const int*)d_in[3];
    const float* feat = (const float*)d_in[4];
    const float* Ws   = (const float*)d_in[5];
    const float* Wa   = (const float*)d_in[6];
    const float* Wd   = (const float*)d_in[7];
    const float* bias = (const float*)d_in[8];
    const float* WC   = (const float*)d_in[9];
    const float* WCb  = (const float*)d_in[10];
    float* out = (float*)d_out;

    static int smem_set = 0;
    if (!smem_set) {
        cudaFuncSetAttribute(gemm_hmma, cudaFuncAttributeMaxDynamicSharedMemorySize, SMEM_GEMM);
        smem_set = 1;
    }

    combine_kernel<<<49, 384>>>(Ws, Wa, Wd, WC, bias, WCb);
    agg_kernel<<<N_UNIQ / 8, 256>>>(uniq, adj, dis, feat);
    gemm_hmma<<<dim3(N_CTAS_M, 3), 256, SMEM_GEMM>>>(N_UNIQ);
    gather_kernel<<<B_OUT / 8, 256>>>(nidx, out);
}

// round 6
// speedup vs baseline: 2.1331x; 1.0655x over previous
#include <cuda_runtime.h>
#include <cuda_bf16.h>
#include <math.h>
#include <stdint.h>

#define N_UNIQ 20000
#define D_IN   128
#define D_OUT  384
#define K_NB   32
#define B_OUT  40000

#define KP        768          // split-K storage: [hi 384 | lo 384]
#define ROWS_PAD  20096        // 157 * 128
#define NCHUNK    36           // 3 segments x 12 chunks of BK=32
#define NGRP      4

// row-group boundaries (nodes) and M-tile boundaries
static const int g_node0[NGRP + 1] = {0, 5120, 10240, 15360, 20000};
static const int g_tile0[NGRP + 1] = {0, 40, 80, 120, 157};

// ---------------- scratch (__device__ globals) ------------------------------
__device__ __align__(128) __nv_bfloat16 g_Xs[ROWS_PAD * KP];  // A, hi|lo
__device__ __align__(128) __nv_bfloat16 g_Bt[D_OUT * KP];     // B [n][k], hi|lo
__device__ __align__(128) float g_c[D_OUT];                   // fused bias
__device__ __align__(128) float g_Z[ROWS_PAD * D_OUT];        // unnormalized out
__device__ __align__(128) float g_ssp[3 * ROWS_PAD];          // per-(yslab,row) sum sq

// ---------------- helpers ----------------------------------------------------
__device__ __forceinline__ uint32_t smem_u32(const void* p) {
    uint32_t a;
    asm("{ .reg .u64 t; cvta.to.shared.u64 t, %1; cvt.u32.u64 %0, t; }" : "=r"(a) : "l"(p));
    return a;
}
#define LDMATRIX_X4(r0, r1, r2, r3, addr) \
    asm volatile("ldmatrix.sync.aligned.m8n8.x4.shared.b16 {%0,%1,%2,%3}, [%4];" \
                 : "=r"(r0), "=r"(r1), "=r"(r2), "=r"(r3) : "r"(addr))
#define MMA_16816(d, a, b0, b1) \
    asm volatile("mma.sync.aligned.m16n8k16.row.col.f32.bf16.bf16.f32 " \
                 "{%0,%1,%2,%3}, {%4,%5,%6,%7}, {%8,%9}, {%0,%1,%2,%3};" \
                 : "+f"((d)[0]), "+f"((d)[1]), "+f"((d)[2]), "+f"((d)[3]) \
                 : "r"((a)[0]), "r"((a)[1]), "r"((a)[2]), "r"((a)[3]), \
                   "r"(b0), "r"(b1))
#define CP_ASYNC_16(dst, src) \
    asm volatile("cp.async.cg.shared.global [%0], [%1], 16;" :: "r"(dst), "l"(src))
#define CP_COMMIT() asm volatile("cp.async.commit_group;" ::: "memory")
#define CP_WAIT2()  asm volatile("cp.async.wait_group 2;" ::: "memory")

// ---------------------------------------------------------------------------
// Kernel 1: fused weight (transposed [n][k], bf16 hi|lo split) + fused bias.
// ---------------------------------------------------------------------------
__global__ __launch_bounds__(384) void combine_kernel(const float* __restrict__ Ws,
                               const float* __restrict__ Wa,
                               const float* __restrict__ Wd,
                               const float* __restrict__ WC,
                               const float* __restrict__ bias,
                               const float* __restrict__ WCb) {
    int j = threadIdx.x;      // output col n (0..383)
    int rb = blockIdx.x;      // 0..47 = 8-row groups, 48 = bias
    if (rb < 48) {
        int r0 = rb * 8;
        int part = r0 >> 7;
        const float* W = (part == 0) ? Ws : ((part == 1) ? Wa : Wd);
        __shared__ float sW[8][128];
        for (int t = j; t < 1024; t += 384) {
            int q = t >> 7, o = t & 127;
            sW[q][o] = W[((r0 & 127) + q) * 128 + o];
        }
        __syncthreads();
        float acc[8] = {0.f, 0.f, 0.f, 0.f, 0.f, 0.f, 0.f, 0.f};
#pragma unroll 4
        for (int o = 0; o < 128; o++) {
            float wc = __ldg(&WC[(part * 128 + o) * D_OUT + j]);
#pragma unroll
            for (int q = 0; q < 8; q++) acc[q] += sW[q][o] * wc;
        }
#pragma unroll
        for (int q = 0; q < 8; q++) {
            __nv_bfloat16 hi = __float2bfloat16(acc[q]);
            __nv_bfloat16 lo = __float2bfloat16(acc[q] - __bfloat162float(hi));
            g_Bt[j * KP + r0 + q] = hi;
            g_Bt[j * KP + 384 + r0 + q] = lo;
        }
    } else {
        float acc = WCb[j];
        for (int i = 0; i < D_OUT; i++)
            acc += bias[i] * WC[i * D_OUT + j];
        g_c[j] = acc;
    }
}

// ---------------------------------------------------------------------------
// Kernel 2: aggregation, warp-per-node (float4 per lane, indices via shfl).
// Processes nodes [node0, node0 + gridDim.x*8).
// ---------------------------------------------------------------------------
__global__ __launch_bounds__(256) void agg_kernel(const int* __restrict__ uniq,
                                                  const int* __restrict__ adj,
                                                  const int* __restrict__ dis,
                                                  const float* __restrict__ feat,
                                                  int node0) {
    const int warp = threadIdx.x >> 5;
    const int lane = threadIdx.x & 31;
    const int n = node0 + blockIdx.x * 8 + warp;

    const int ia = __ldg(&adj[n * K_NB + lane]);
    const int id = __ldg(&dis[n * K_NB + lane]);
    const int iu = __ldg(&uniq[n]);

    const float4* f4 = reinterpret_cast<const float4*>(feat);

    float4 a = make_float4(0.f, 0.f, 0.f, 0.f);
    float4 b = make_float4(0.f, 0.f, 0.f, 0.f);
#pragma unroll
    for (int k = 0; k < K_NB; k++) {
        int ra = __shfl_sync(0xffffffffu, ia, k);
        int rd = __shfl_sync(0xffffffffu, id, k);
        float4 va = __ldg(&f4[(size_t)ra * 32 + lane]);
        float4 vb = __ldg(&f4[(size_t)rd * 32 + lane]);
        a.x += va.x; a.y += va.y; a.z += va.z; a.w += va.w;
        b.x += vb.x; b.y += vb.y; b.z += vb.z; b.w += vb.w;
    }
    float4 sf = __ldg(&f4[(size_t)iu * 32 + lane]);
    const float inv = 1.f / 32.f;
    a.x *= inv; a.y *= inv; a.z *= inv; a.w *= inv;
    b.x *= inv; b.y *= inv; b.z *= inv; b.w *= inv;

    __nv_bfloat16* row = &g_Xs[(size_t)n * KP];
    auto store_seg = [&](int base, float4 v) {
        __nv_bfloat16 h[4], l[4];
        float vv[4] = {v.x, v.y, v.z, v.w};
#pragma unroll
        for (int q = 0; q < 4; q++) {
            h[q] = __float2bfloat16(vv[q]);
            l[q] = __float2bfloat16(vv[q] - __bfloat162float(h[q]));
        }
        *reinterpret_cast<uint2*>(&row[base + lane * 4])       = *reinterpret_cast<uint2*>(h);
        *reinterpret_cast<uint2*>(&row[384 + base + lane * 4]) = *reinterpret_cast<uint2*>(l);
    };
    store_seg(0, sf);
    store_seg(128, a);
    store_seg(256, b);
}

// ---------------------------------------------------------------------------
// Kernel 3: HMMA GEMM, 4-stage cp.async pipeline. Grid (tiles_g, 3).
// CTA 128x128, 8 warps (4Mx2N) m32xn64 each, BK=32, LDROW=80.
// ---------------------------------------------------------------------------
#define LDROW   80
#define STG     (128 * LDROW)     // 10240 B per operand stage
#define SMEM_GEMM (4 * 2 * STG)   // 81920

__global__ __launch_bounds__(256, 2) void gemm_hmma(int tile0) {
    extern __shared__ __align__(128) char dsm[];
    const uint32_t sbase = smem_u32(dsm);
    const uint32_t aarea = sbase;
    const uint32_t barea = sbase + 4 * STG;

    const int tid   = threadIdx.x;
    const int lane  = tid & 31;
    const int wid   = tid >> 5;
    const int warpM = wid & 3;
    const int warpN = wid >> 2;
    const int row0  = (tile0 + blockIdx.x) * 128;
    const int n0    = blockIdx.y * 128;

    float acc[2][8][4];
#pragma unroll
    for (int mt = 0; mt < 2; mt++)
#pragma unroll
        for (int nt = 0; nt < 8; nt++)
#pragma unroll
            for (int q = 0; q < 4; q++) acc[mt][nt][q] = 0.f;

    const int ldr = tid >> 2;   // 0..63
    const int ldu = tid & 3;    // 0..3

    auto issue_stage = [&](int c) {
        int s = c & 3;
        int seg = c / 12, i = c % 12;
        int abase = ((seg == 1) ? 384 : 0) + i * 32;
        int bbase = ((seg == 2) ? 384 : 0) + i * 32;
        uint32_t da = aarea + s * STG;
        uint32_t db = barea + s * STG;
#pragma unroll
        for (int it = 0; it < 2; it++) {
            int r = ldr + it * 64;
            CP_ASYNC_16(da + r * LDROW + ldu * 16,
                        (const void*)&g_Xs[(size_t)(row0 + r) * KP + abase + ldu * 8]);
            CP_ASYNC_16(db + r * LDROW + ldu * 16,
                        (const void*)&g_Bt[(size_t)r * KP + n0 * 0 + bbase + ldu * 8 + (size_t)n0 * KP]);
        }
    };

    const int lq = lane >> 3, lr = lane & 7;
    const int a_mrow = warpM * 32 + (lq & 1) * 8 + lr;
    const int a_koff = (lq >> 1) * 8;
    const int b_nrow = warpN * 64 + (lq >> 1) * 8 + lr;
    const int b_koff = (lq & 1) * 8;

#pragma unroll
    for (int s = 0; s < 3; s++) { issue_stage(s); CP_COMMIT(); }

    for (int c = 0; c < NCHUNK; c++) {
        CP_WAIT2();
        __syncthreads();
        if (c + 3 < NCHUNK) issue_stage(c + 3);
        CP_COMMIT();

        const int s = c & 3;
        const uint32_t abuf = aarea + s * STG;
        const uint32_t bbuf = barea + s * STG;
#pragma unroll
        for (int ks = 0; ks < 2; ks++) {
            uint32_t a[2][4];
#pragma unroll
            for (int mt = 0; mt < 2; mt++) {
                uint32_t addr = abuf + (a_mrow + mt * 16) * LDROW + (ks * 16 + a_koff) * 2;
                LDMATRIX_X4(a[mt][0], a[mt][1], a[mt][2], a[mt][3], addr);
            }
            uint32_t b[4][4];
#pragma unroll
            for (int np = 0; np < 4; np++) {
                uint32_t addr = bbuf + (b_nrow + np * 16) * LDROW + (ks * 16 + b_koff) * 2;
                LDMATRIX_X4(b[np][0], b[np][1], b[np][2], b[np][3], addr);
            }
#pragma unroll
            for (int mt = 0; mt < 2; mt++)
#pragma unroll
                for (int np = 0; np < 4; np++) {
                    MMA_16816(acc[mt][np * 2 + 0], a[mt], b[np][0], b[np][1]);
                    MMA_16816(acc[mt][np * 2 + 1], a[mt], b[np][2], b[np][3]);
                }
        }
    }

    // ---- epilogue ----
    const int g  = lane >> 2;
    const int cq = lane & 3;
    float ssA[2], ssB[2];
#pragma unroll
    for (int mt = 0; mt < 2; mt++) {
        const int rbase = row0 + warpM * 32 + mt * 16;
        float ss0 = 0.f, ss1 = 0.f;
#pragma unroll
        for (int nt = 0; nt < 8; nt++) {
            int col = n0 + warpN * 64 + nt * 8 + cq * 2;
            float b0 = __ldg(&g_c[col]);
            float b1 = __ldg(&g_c[col + 1]);
            float z0 = acc[mt][nt][0] + b0; z0 = (z0 >= 0.f) ? z0 : 0.2f * z0;
            float z1 = acc[mt][nt][1] + b1; z1 = (z1 >= 0.f) ? z1 : 0.2f * z1;
            float z2 = acc[mt][nt][2] + b0; z2 = (z2 >= 0.f) ? z2 : 0.2f * z2;
            float z3 = acc[mt][nt][3] + b1; z3 = (z3 >= 0.f) ? z3 : 0.2f * z3;
            *reinterpret_cast<float2*>(&g_Z[(size_t)(rbase + g) * D_OUT + col])     = make_float2(z0, z1);
            *reinterpret_cast<float2*>(&g_Z[(size_t)(rbase + g + 8) * D_OUT + col]) = make_float2(z2, z3);
            ss0 += z0 * z0 + z1 * z1;
            ss1 += z2 * z2 + z3 * z3;
        }
        ss0 += __shfl_xor_sync(0xffffffffu, ss0, 1);
        ss0 += __shfl_xor_sync(0xffffffffu, ss0, 2);
        ss1 += __shfl_xor_sync(0xffffffffu, ss1, 1);
        ss1 += __shfl_xor_sync(0xffffffffu, ss1, 2);
        ssA[mt] = ss0;
        ssB[mt] = ss1;
    }
    __syncthreads();
    float* s_ss = reinterpret_cast<float*>(dsm);
    if (tid < 128) s_ss[tid] = 0.f;
    __syncthreads();
    if (cq == 0) {
#pragma unroll
        for (int mt = 0; mt < 2; mt++) {
            atomicAdd(&s_ss[warpM * 32 + mt * 16 + g],     ssA[mt]);
            atomicAdd(&s_ss[warpM * 32 + mt * 16 + 8 + g], ssB[mt]);
        }
    }
    __syncthreads();
    if (tid < 128) g_ssp[(size_t)blockIdx.y * ROWS_PAD + row0 + tid] = s_ss[tid];
}

// ---------------------------------------------------------------------------
// Kernel 4: normalize + batch gather. Warp per output row, MLP 3.
// ---------------------------------------------------------------------------
__global__ __launch_bounds__(256) void gather_kernel(const int* __restrict__ nidx,
                                                     float* __restrict__ out) {
    const int warp = threadIdx.x >> 5;
    const int lane = threadIdx.x & 31;
    const int b = blockIdx.x * 8 + warp;
    const int idx = __ldg(&nidx[b]);
    const float s = __ldg(&g_ssp[idx]) + __ldg(&g_ssp[ROWS_PAD + idx]) +
                    __ldg(&g_ssp[2 * ROWS_PAD + idx]);
    const float inv = 1.f / fmaxf(sqrtf(s), 1e-12f);

    const float4* zp = reinterpret_cast<const float4*>(&g_Z[(size_t)idx * D_OUT]);
    float4* op = reinterpret_cast<float4*>(&out[(size_t)b * D_OUT]);
    float4 v0 = __ldg(&zp[lane]);
    float4 v1 = __ldg(&zp[lane + 32]);
    float4 v2 = __ldg(&zp[lane + 64]);
    v0.x *= inv; v0.y *= inv; v0.z *= inv; v0.w *= inv;
    v1.x *= inv; v1.y *= inv; v1.z *= inv; v1.w *= inv;
    v2.x *= inv; v2.y *= inv; v2.z *= inv; v2.w *= inv;
    op[lane]      = v0;
    op[lane + 32] = v1;
    op[lane + 64] = v2;
}

// ---------------------------------------------------------------------------
// Stream/event resources created once at static-init time (no allocation
// inside kernel_launch / capture).
// ---------------------------------------------------------------------------
static cudaStream_t s_aggS, s_gemmS;
static cudaEvent_t  s_evRoot, s_evAgg[NGRP], s_evJoin;
struct _ResInit {
    _ResInit() {
        cudaStreamCreateWithFlags(&s_aggS,  cudaStreamNonBlocking);
        cudaStreamCreateWithFlags(&s_gemmS, cudaStreamNonBlocking);
        cudaEventCreateWithFlags(&s_evRoot, cudaEventDisableTiming);
        for (int g = 0; g < NGRP; g++)
            cudaEventCreateWithFlags(&s_evAgg[g], cudaEventDisableTiming);
        cudaEventCreateWithFlags(&s_evJoin, cudaEventDisableTiming);
        cudaFuncSetAttribute(gemm_hmma, cudaFuncAttributeMaxDynamicSharedMemorySize, SMEM_GEMM);
    }
};
static _ResInit s_resInit;

// ---------------------------------------------------------------------------
extern "C" void kernel_launch(void* const* d_in, const int* in_sizes, int n_in,
                              void* d_out, int out_size) {
    const int*   uniq = (const int*)d_in[0];
    const int*   adj  = (const int*)d_in[1];
    const int*   dis  = (const int*)d_in[2];
    const int*   nidx = (const int*)d_in[3];
    const float* feat = (const float*)d_in[4];
    const float* Ws   = (const float*)d_in[5];
    const float* Wa   = (const float*)d_in[6];
    const float* Wd   = (const float*)d_in[7];
    const float* bias = (const float*)d_in[8];
    const float* WC   = (const float*)d_in[9];
    const float* WCb  = (const float*)d_in[10];
    float* out = (float*)d_out;

    // fork from the (captured) legacy stream
    cudaEventRecord(s_evRoot, 0);
    cudaStreamWaitEvent(s_aggS,  s_evRoot, 0);
    cudaStreamWaitEvent(s_gemmS, s_evRoot, 0);

    // combine runs concurrently with agg on the gemm stream
    combine_kernel<<<49, 384, 0, s_gemmS>>>(Ws, Wa, Wd, WC, bias, WCb);

    // agg groups on stream A, each records an event
    for (int g = 0; g < NGRP; g++) {
        int nodes = g_node0[g + 1] - g_node0[g];
        agg_kernel<<<nodes / 8, 256, 0, s_aggS>>>(uniq, adj, dis, feat, g_node0[g]);
        cudaEventRecord(s_evAgg[g], s_aggS);
    }
    // gemm groups on stream B, each gated on its agg group
    for (int g = 0; g < NGRP; g++) {
        int tiles = g_tile0[g + 1] - g_tile0[g];
        cudaStreamWaitEvent(s_gemmS, s_evAgg[g], 0);
        gemm_hmma<<<dim3(tiles, 3), 256, SMEM_GEMM, s_gemmS>>>(g_tile0[g]);
    }

    // join back to legacy stream, then gather
    cudaEventRecord(s_evJoin, s_gemmS);
    cudaStreamWaitEvent(0, s_evJoin, 0);
    gather_kernel<<<B_OUT / 8, 256>>>(nidx, out);
}